// round 17
// baseline (speedup 1.0000x reference)
#include <cuda_runtime.h>
#include <cstdint>
#include <cstddef>

// PHMLinear via mma.sync tf32 — small-CTA high-occupancy version.
// 8 rows/CTA (grid 1024), 128 threads / 4 warps, 1 m-tile per warp.
// Weights fully pre-transformed by prep kernel (transposed + pair-permuted
// so MMA B-fragments are single LDS.64 loads and staging is float4 copies).

__device__ float g_wrlP[32 * 128];   // [er][p], p-permuted: pairs (i, i+4) adjacent
__device__ float g_wrrP[128 * 32];   // [o][p],  p-permuted: pairs (er, er+4) adjacent
__device__ float g_wl[512];          // [e][c][a]

__device__ __forceinline__ uint32_t to_tf32(float f) {
    uint32_t r;
    asm("cvt.rna.tf32.f32 %0, %1;" : "=r"(r) : "f"(f));
    return r;
}

__global__ void phm_prep(const float* __restrict__ wrl,
                         const float* __restrict__ wrr,
                         const float* __restrict__ wlf) {
    int idx = blockIdx.x * blockDim.x + threadIdx.x;
    if (idx < 4096) {
        // g_wrlP[er][p]: p = kc*32+kt*8+2*tg+d  <->  i = kc*32+kt*8+tg+4*d
        int er = idx >> 7, p = idx & 127;
        int q = p & 7;
        int i = (p & ~7) | ((q >> 1) + ((q & 1) << 2));
        int e = er >> 2, r = er & 3;
        g_wrlP[idx] = __uint_as_float(to_tf32(wrl[e * 512 + i * 4 + r]));
    }
    if (idx < 4096) {
        // g_wrrP[o][p]: p = kt*8+2*tg+d  <->  er = kt*8+tg+4*d
        int o = idx >> 5, p = idx & 31;
        int q = p & 7;
        int er = (p & ~7) | ((q >> 1) + ((q & 1) << 2));
        g_wrrP[idx] = __uint_as_float(to_tf32(wrr[er * 128 + o]));
    }
    if (idx < 512) {
        int e = idx >> 6, c = (idx >> 3) & 7, a = idx & 7;
        g_wl[idx] = wlf[e * 64 + a * 8 + c];
    }
}

__device__ __forceinline__ void mma8(float& d0, float& d1, float& d2, float& d3,
                                     uint32_t a0, uint32_t a1, uint32_t a2, uint32_t a3,
                                     uint32_t b0, uint32_t b1) {
    asm volatile(
        "mma.sync.aligned.m16n8k8.row.col.f32.tf32.tf32.f32 "
        "{%0,%1,%2,%3}, {%4,%5,%6,%7}, {%8,%9}, {%0,%1,%2,%3};"
        : "+f"(d0), "+f"(d1), "+f"(d2), "+f"(d3)
        : "r"(a0), "r"(a1), "r"(a2), "r"(a3), "r"(b0), "r"(b1));
}

__global__ void __launch_bounds__(128, 5)
phm_tc(const float* __restrict__ x,
       float* __restrict__ out,
       int nrows)
{
    // Region A: per-warp x chunk [64 vrow][36] -> y1T [32 er][64 vrow pad68]
    __shared__ __align__(16) float sA[2304];
    // Region B: WrlP [32 er][128 pad132] -> WrrP [128 o][32 pad36]
    __shared__ __align__(16) float sB[4608];
    __shared__ __align__(16) float s_wl[512];   // [e][c][a]

    const int tid  = threadIdx.x;
    const int lane = tid & 31;
    const int wid  = tid >> 5;
    const int g  = lane >> 2;   // mma groupID
    const int tg = lane & 3;    // mma threadID-in-group
    int row0 = blockIdx.x * 8;
    if (row0 >= nrows) return;

    // ---- stage WrlP [er][132] + wl (float4 copies) ----
    #pragma unroll
    for (int k = 0; k < 8; k++) {
        int f4 = tid + 128 * k;                // 1024 float4
        int er = f4 >> 5, p4 = f4 & 31;
        *(float4*)(sB + er * 132 + p4 * 4) = *(const float4*)(g_wrlP + er * 128 + p4 * 4);
    }
    if (tid < 128)
        *(float4*)(s_wl + tid * 4) = *(const float4*)(g_wl + tid * 4);
    __syncthreads();   // block sync #1

    const int mbase = wid * 16;                // warp-own vrows [mbase, mbase+16)

    // x staging map (conflict-free STS.128 + coalesced LDG.128):
    // f4 = lane + 32k -> vrow = mbase + (f4>>3), i4 = f4&7
    // quarter-warp: one vrow, i4 = 0..7 -> 32 consecutive floats (all banks) and
    // one contiguous 128B global line.

    // ---- MMA1 with register-prefetched per-warp staging ----
    float y[4][4];
    #pragma unroll
    for (int nt = 0; nt < 4; nt++)
        #pragma unroll
        for (int j = 0; j < 4; j++) y[nt][j] = 0.0f;

    float4 xq[4];
    #pragma unroll
    for (int k = 0; k < 4; k++) {
        int f4 = lane + 32 * k;
        int vrow = mbase + (f4 >> 3);
        int i4 = f4 & 7;
        int row = row0 + (vrow >> 3);
        if (row >= nrows) row = nrows - 1;
        xq[k] = *(const float4*)(x + (size_t)row * 1024 + (vrow & 7) * 128 + i4 * 4);
    }

    #pragma unroll 1
    for (int kc = 0; kc < 4; kc++) {
        #pragma unroll
        for (int k = 0; k < 4; k++) {
            int f4 = lane + 32 * k;
            int vrow = mbase + (f4 >> 3);
            int i4 = f4 & 7;
            float4 v = xq[k];
            v.x = __uint_as_float(to_tf32(v.x));
            v.y = __uint_as_float(to_tf32(v.y));
            v.z = __uint_as_float(to_tf32(v.z));
            v.w = __uint_as_float(to_tf32(v.w));
            *(float4*)(sA + vrow * 36 + i4 * 4) = v;
        }
        __syncwarp();

        if (kc < 3) {
            #pragma unroll
            for (int k = 0; k < 4; k++) {
                int f4 = lane + 32 * k;
                int vrow = mbase + (f4 >> 3);
                int i4 = f4 & 7;
                int row = row0 + (vrow >> 3);
                if (row >= nrows) row = nrows - 1;
                xq[k] = *(const float4*)(x + (size_t)row * 1024 + (vrow & 7) * 128
                                           + (kc + 1) * 32 + i4 * 4);
            }
        }

        #pragma unroll
        for (int kt = 0; kt < 4; kt++) {
            const float* xa = sA + mbase * 36 + kt * 8 + tg;
            uint32_t a0 = __float_as_uint(xa[g * 36]);
            uint32_t a1 = __float_as_uint(xa[(g + 8) * 36]);
            uint32_t a2 = __float_as_uint(xa[g * 36 + 4]);
            uint32_t a3 = __float_as_uint(xa[(g + 8) * 36 + 4]);
            #pragma unroll
            for (int nt = 0; nt < 4; nt++) {
                float2 bp = *(const float2*)(sB + (nt * 8 + g) * 132 + kc * 32 + kt * 8 + 2 * tg);
                mma8(y[nt][0], y[nt][1], y[nt][2], y[nt][3],
                     a0, a1, a2, a3, __float_as_uint(bp.x), __float_as_uint(bp.y));
            }
        }
        __syncwarp();
    }

    __syncthreads();   // block sync #2: MMA1 done everywhere; x + WrlP dead

    // ---- y1T [er][vrow pad68] into region A ----
    #pragma unroll
    for (int nt = 0; nt < 4; nt++) {
        int vr = mbase + g;
        int er = nt * 8 + tg * 2;
        sA[er * 68 + vr]           = y[nt][0];
        sA[(er + 1) * 68 + vr]     = y[nt][1];
        sA[er * 68 + vr + 8]       = y[nt][2];
        sA[(er + 1) * 68 + vr + 8] = y[nt][3];
    }
    // ---- WrrP [o][32 pad36] into region B ----
    #pragma unroll
    for (int k = 0; k < 8; k++) {
        int f4 = tid + 128 * k;                // 1024 float4
        int o = f4 >> 3, e4 = f4 & 7;
        *(float4*)(sB + o * 36 + e4 * 4) = *(const float4*)(g_wrrP + o * 32 + e4 * 4);
    }
    __syncthreads();   // block sync #3

    // ---- Phase B: uu[rp][e]; er = 4e+tg; t = mbase+rp*8+g -> row 2wid+rp, c=g ----
    uint32_t uu[2][8];
    #pragma unroll
    for (int e = 0; e < 8; e++) {
        int er = 4 * e + tg;
        float4 w0 = *(const float4*)(s_wl + e * 64 + g * 8);
        float4 w1 = *(const float4*)(s_wl + e * 64 + g * 8 + 4);
        #pragma unroll
        for (int rp = 0; rp < 2; rp++) {
            int vb = mbase + rp * 8;
            float4 y0 = *(const float4*)(sA + er * 68 + vb);
            float4 y1v = *(const float4*)(sA + er * 68 + vb + 4);
            float u = y0.x * w0.x + y0.y * w0.y + y0.z * w0.z + y0.w * w0.w
                    + y1v.x * w1.x + y1v.y * w1.y + y1v.z * w1.z + y1v.w * w1.w;
            uu[rp][e] = to_tf32(u);
        }
    }

    // ---- MMA2 + direct STG epilogue ----
    const int r0g = row0 + 2 * wid;
    bool ok0 = r0g < nrows;
    bool ok1 = (r0g + 1) < nrows;
    float* og0 = out + (size_t)r0g * 1024;
    float* og1 = out + (size_t)(r0g + 1) * 1024;

    #pragma unroll 1
    for (int qn = 0; qn < 4; qn++) {
        float d[4][4];
        #pragma unroll
        for (int nl = 0; nl < 4; nl++)
            #pragma unroll
            for (int j = 0; j < 4; j++) d[nl][j] = 0.0f;

        #pragma unroll
        for (int kt = 0; kt < 4; kt++) {
            uint32_t a0 = uu[0][2 * kt],     a1 = uu[1][2 * kt];
            uint32_t a2 = uu[0][2 * kt + 1], a3 = uu[1][2 * kt + 1];
            #pragma unroll
            for (int nl = 0; nl < 4; nl++) {
                int o = qn * 32 + nl * 8 + g;
                float2 bp = *(const float2*)(sB + o * 36 + kt * 8 + 2 * tg);
                mma8(d[nl][0], d[nl][1], d[nl][2], d[nl][3],
                     a0, a1, a2, a3, __float_as_uint(bp.x), __float_as_uint(bp.y));
            }
        }

        #pragma unroll
        for (int nl = 0; nl < 4; nl++) {
            int col = (qn * 32 + nl * 8 + 2 * tg) * 8 + g;
            if (ok0) {
                og0[col]     = d[nl][0];
                og0[col + 8] = d[nl][1];
            }
            if (ok1) {
                og1[col]     = d[nl][2];
                og1[col + 8] = d[nl][3];
            }
        }
    }
}

extern "C" void kernel_launch(void* const* d_in, const int* in_sizes, int n_in,
                              void* d_out, int out_size) {
    const float* x   = (const float*)d_in[0];
    const float* wrl = (const float*)d_in[1];
    const float* wrr = (const float*)d_in[2];
    const float* wlf = (const float*)d_in[3];
    float* out = (float*)d_out;

    int nrows = in_sizes[0] / 1024;          // B*S = 8192
    phm_prep<<<16, 256>>>(wrl, wrr, wlf);
    int grid = (nrows + 7) / 8;              // 8 rows per CTA
    phm_tc<<<grid, 128>>>(x, out, nrows);
}